// round 15
// baseline (speedup 1.0000x reference)
#include <cuda_runtime.h>
#include <cuda_bf16.h>
#include <cstdint>
#include <cstddef>

// Problem constants
#define T_  2048
#define B_  256
#define I_  64
#define H_  128
#define G_  512          // 4*H gate rows
#define NH_ 512
#define O_  64
#define TB_ (T_ * B_)    // 524288

// ---------------------------------------------------------------------------
// f32x2 packed helpers (scan)
// ---------------------------------------------------------------------------
__device__ __forceinline__ void fma2(unsigned long long& d,
                                     unsigned long long a,
                                     unsigned long long b) {
    asm("fma.rn.f32x2 %0, %1, %2, %0;" : "+l"(d) : "l"(a), "l"(b));
}
__device__ __forceinline__ void unpack2(unsigned long long v, float& lo, float& hi) {
    asm("mov.b64 {%0, %1}, %2;" : "=f"(lo), "=f"(hi) : "l"(v));
}
__device__ __forceinline__ float hadd2(unsigned long long v) {
    float lo, hi; unpack2(v, lo, hi); return lo + hi;
}

__device__ __forceinline__ uint32_t smem_u32(const void* p) {
    uint32_t a;
    asm("{ .reg .u64 t; cvta.to.shared.u64 t, %1; cvt.u32.u64 %0, t; }"
        : "=r"(a) : "l"(p));
    return a;
}

// pack 2 floats -> bf16x2 (lo in low half)
__device__ __forceinline__ uint32_t pkbf2(float lo, float hi) {
    __nv_bfloat162 t = __floats2bfloat162_rn(lo, hi);
    return *(uint32_t*)&t;
}
__device__ __forceinline__ float tobf(float v) {
    return __bfloat162float(__float2bfloat16(v));
}

// split float4 into bf16 hi quad + bf16 lo (residual) quad
__device__ __forceinline__ void split4(float4 v, uint2& hi, uint2& lo) {
    float hx = tobf(v.x), hy = tobf(v.y), hz = tobf(v.z), hw = tobf(v.w);
    hi = make_uint2(pkbf2(hx, hy), pkbf2(hz, hw));
    lo = make_uint2(pkbf2(v.x - hx, v.y - hy), pkbf2(v.z - hz, v.w - hw));
}

// ldmatrix x4 (no trans)
__device__ __forceinline__ void ldx4(uint32_t& r0, uint32_t& r1,
                                     uint32_t& r2, uint32_t& r3, uint32_t addr) {
    asm volatile("ldmatrix.sync.aligned.m8n8.x4.shared.b16 {%0,%1,%2,%3}, [%4];"
        : "=r"(r0), "=r"(r1), "=r"(r2), "=r"(r3) : "r"(addr));
}

// bf16 mma m16n8k16, fp32 accumulate
__device__ __forceinline__ void mma16816(float* d,
                                         uint32_t a0, uint32_t a1,
                                         uint32_t a2, uint32_t a3,
                                         uint32_t b0, uint32_t b1) {
    asm volatile(
        "mma.sync.aligned.m16n8k16.row.col.f32.bf16.bf16.f32 "
        "{%0,%1,%2,%3}, {%4,%5,%6,%7}, {%8,%9}, {%0,%1,%2,%3};"
        : "+f"(d[0]), "+f"(d[1]), "+f"(d[2]), "+f"(d[3])
        : "r"(a0), "r"(a1), "r"(a2), "r"(a3), "r"(b0), "r"(b1));
}

// ---------------------------------------------------------------------------
// Scratch: __device__ globals (allocation-free rule).
// ---------------------------------------------------------------------------
__device__ float  g_xg[(size_t)TB_ * G_];   // gate preacts from input projection
__device__ float  g_hs[(size_t)TB_ * H_];   // all hidden states
__device__ float4 g_wt4[32 * G_];           // W_hh k-chunked

// ---------------------------------------------------------------------------
// K0: transpose W_hh [512,128] -> g_wt4
// ---------------------------------------------------------------------------
__global__ void k_twhh(const float* __restrict__ Whh) {
    int idx = blockIdx.x * 256 + threadIdx.x;
    int g = idx >> 7;
    int k = idx & 127;
    ((float*)g_wt4)[((k >> 2) * G_ + g) * 4 + (k & 3)] = Whh[idx];
}

// ---------------------------------------------------------------------------
// HMMA GEMM (K1 only): C = A@W^T + bias + bias2.
// CTA 128x64, BK=32, 8 warps (4m x 2n), double buffered. (Proven R12 kernel.)
// ---------------------------------------------------------------------------
#define LDB 80
#define ASZ (128 * LDB)
#define WSZ (64 * LDB)
#define BUF (2 * ASZ + 2 * WSZ)
#define HG_SMEM (2 * BUF)

template <bool RELU>
__global__ __launch_bounds__(256, 2) void k_hgemm(
    const float* __restrict__ A, const float* __restrict__ W,
    const float* __restrict__ bias, const float* __restrict__ bias2,
    float* __restrict__ C, int M, int N, int K)
{
    extern __shared__ char smem[];
    const uint32_t sb = smem_u32(smem);
    const uint32_t AHo = 0, ALo = ASZ, WHo = 2 * ASZ, WLo = 2 * ASZ + WSZ;

    const int tid  = threadIdx.x;
    const int wid  = tid >> 5;
    const int lane = tid & 31;
    const int wm   = wid & 3;
    const int wn   = wid >> 2;
    const int m0   = blockIdx.x * 128;
    const int n0   = blockIdx.y * 64;

    const int am = tid >> 3;
    const int akq = (tid & 7) * 4;

    const uint32_t a_off = (uint32_t)((wm * 32 + (lane & 7) + ((lane >> 3) & 1) * 8) * LDB
                                      + (lane >> 4) * 16);
    const uint32_t b_off = (uint32_t)((wn * 32 + (lane & 7) + (lane >> 4) * 8) * LDB
                                      + ((lane >> 3) & 1) * 16);

    float acc[2][4][4];
#pragma unroll
    for (int i = 0; i < 2; i++)
#pragma unroll
        for (int j = 0; j < 4; j++)
#pragma unroll
            for (int q = 0; q < 4; q++) acc[i][j][q] = 0.f;

    float4 pa[4], pw[2];
#pragma unroll
    for (int r = 0; r < 4; r++)
        pa[r] = *(const float4*)&A[(size_t)(m0 + am + 32 * r) * K + akq];
#pragma unroll
    for (int r = 0; r < 2; r++) {
        int idx = tid + 256 * r;
        pw[r] = *(const float4*)&W[(size_t)(n0 + (idx >> 3)) * K + (idx & 7) * 4];
    }

    auto stage = [&](int buf, const float4* va, const float4* vw) {
        uint32_t bo = buf * BUF;
#pragma unroll
        for (int r = 0; r < 4; r++) {
            uint2 hi, lo;
            split4(va[r], hi, lo);
            uint32_t off = (uint32_t)((am + 32 * r) * LDB + akq * 2);
            *(uint2*)(smem + bo + AHo + off) = hi;
            *(uint2*)(smem + bo + ALo + off) = lo;
        }
#pragma unroll
        for (int r = 0; r < 2; r++) {
            int idx = tid + 256 * r;
            uint2 hi, lo;
            split4(vw[r], hi, lo);
            uint32_t off = (uint32_t)((idx >> 3) * LDB + (idx & 7) * 8);
            *(uint2*)(smem + bo + WHo + off) = hi;
            *(uint2*)(smem + bo + WLo + off) = lo;
        }
    };

    stage(0, pa, pw);
    __syncthreads();

    const int nt = K / 32;
    for (int t = 0; t < nt; t++) {
        const int cur = t & 1;
        const bool more = (t + 1 < nt);

        if (more) {
            const float* Ap = A + (t + 1) * 32;
            const float* Wp = W + (t + 1) * 32;
#pragma unroll
            for (int r = 0; r < 4; r++)
                pa[r] = *(const float4*)&Ap[(size_t)(m0 + am + 32 * r) * K + akq];
#pragma unroll
            for (int r = 0; r < 2; r++) {
                int idx = tid + 256 * r;
                pw[r] = *(const float4*)&Wp[(size_t)(n0 + (idx >> 3)) * K + (idx & 7) * 4];
            }
        }

        const uint32_t bufb = sb + cur * BUF;
#pragma unroll
        for (int s = 0; s < 2; s++) {
            const uint32_t ks = s * 32;
            uint32_t ah[2][4], al[2][4];
            ldx4(ah[0][0], ah[0][1], ah[0][2], ah[0][3], bufb + AHo + a_off + ks);
            ldx4(ah[1][0], ah[1][1], ah[1][2], ah[1][3], bufb + AHo + a_off + 16 * LDB + ks);
            ldx4(al[0][0], al[0][1], al[0][2], al[0][3], bufb + ALo + a_off + ks);
            ldx4(al[1][0], al[1][1], al[1][2], al[1][3], bufb + ALo + a_off + 16 * LDB + ks);
            uint32_t wh[2][4], wl[2][4];
            ldx4(wh[0][0], wh[0][1], wh[0][2], wh[0][3], bufb + WHo + b_off + ks);
            ldx4(wh[1][0], wh[1][1], wh[1][2], wh[1][3], bufb + WHo + b_off + 16 * LDB + ks);
            ldx4(wl[0][0], wl[0][1], wl[0][2], wl[0][3], bufb + WLo + b_off + ks);
            ldx4(wl[1][0], wl[1][1], wl[1][2], wl[1][3], bufb + WLo + b_off + 16 * LDB + ks);

#pragma unroll
            for (int mf = 0; mf < 2; mf++)
#pragma unroll
                for (int nf = 0; nf < 4; nf++) {
                    const int p = nf >> 1, q = (nf & 1) * 2;
                    mma16816(acc[mf][nf], ah[mf][0], ah[mf][1], ah[mf][2], ah[mf][3],
                             wh[p][q], wh[p][q + 1]);
                    mma16816(acc[mf][nf], al[mf][0], al[mf][1], al[mf][2], al[mf][3],
                             wh[p][q], wh[p][q + 1]);
                    mma16816(acc[mf][nf], ah[mf][0], ah[mf][1], ah[mf][2], ah[mf][3],
                             wl[p][q], wl[p][q + 1]);
                }
        }

        if (more) {
            stage(cur ^ 1, pa, pw);
            __syncthreads();
        }
    }

#pragma unroll
    for (int mf = 0; mf < 2; mf++) {
#pragma unroll
        for (int nf = 0; nf < 4; nf++) {
            int col = n0 + wn * 32 + nf * 8 + (lane & 3) * 2;
            float b0v = bias[col], b1v = bias[col + 1];
            if (bias2) { b0v += bias2[col]; b1v += bias2[col + 1]; }
            int row0 = m0 + wm * 32 + mf * 16 + (lane >> 2);
            float2 o0, o1;
            o0.x = acc[mf][nf][0] + b0v; o0.y = acc[mf][nf][1] + b1v;
            o1.x = acc[mf][nf][2] + b0v; o1.y = acc[mf][nf][3] + b1v;
            if (RELU) {
                o0.x = fmaxf(o0.x, 0.f); o0.y = fmaxf(o0.y, 0.f);
                o1.x = fmaxf(o1.x, 0.f); o1.y = fmaxf(o1.y, 0.f);
            }
            *(float2*)&C[(size_t)row0 * N + col] = o0;
            *(float2*)&C[(size_t)(row0 + 8) * N + col] = o1;
        }
    }
}

// ---------------------------------------------------------------------------
// Fused MLP: out = relu(hs@W1^T + b1)@W2^T + b2, hidden never leaves regs.
// CTA = 128 rows, 8 warps x 16 rows. 4 chunks of 128 hidden cols.
// First-gemm C-frags are reinterpreted as second-gemm A-frags (layout match).
// 3-term bf16 split throughout.
// ---------------------------------------------------------------------------
#define LDW 272                        // 128 bf16 + 16B pad (conflict-free ldmatrix)
#define MHSH 0
#define MHSL (MHSH + 128 * LDW)        // 34816
#define MW1H (MHSL + 128 * LDW)        // 69632
#define MW1L (MW1H + 128 * LDW)        // 104448
#define MW2H (MW1L + 128 * LDW)        // 139264
#define MW2L (MW2H + 64 * LDW)         // 156672
#define MB1  (MW2L + 64 * LDW)         // 174080
#define MB2  (MB1 + 2048)              // 176128
#define MLP_SMEM (MB2 + 256)           // 176384

__global__ __launch_bounds__(256, 1) void k_mlp(
    const float* __restrict__ hs, const float* __restrict__ W1,
    const float* __restrict__ b1, const float* __restrict__ W2,
    const float* __restrict__ b2, float* __restrict__ out)
{
    extern __shared__ char smem[];
    const uint32_t sb = smem_u32(smem);
    float* b1s = (float*)(smem + MB1);
    float* b2s = (float*)(smem + MB2);

    const int tid  = threadIdx.x;
    const int w    = tid >> 5;        // warp 0..7 -> rows [16w,16w+16)
    const int lane = tid & 31;
    const int m0   = blockIdx.x * 128;

    // ldmatrix offsets
    const uint32_t a_off = (uint32_t)((w * 16 + (lane & 7) + ((lane >> 3) & 1) * 8) * LDW
                                      + (lane >> 4) * 16);
    const uint32_t b_off = (uint32_t)(((lane & 7) + (lane >> 4) * 8) * LDW
                                      + ((lane >> 3) & 1) * 16);

    // ---- stage hs tile [128 x 128] as bf16 hi/lo + biases ----
#pragma unroll
    for (int r = 0; r < 16; r++) {
        int idx = tid + 256 * r;
        int row = idx >> 5, kq = (idx & 31) * 4;
        float4 v = *(const float4*)&hs[(size_t)(m0 + row) * H_ + kq];
        uint2 hi, lo; split4(v, hi, lo);
        uint32_t off = (uint32_t)(row * LDW + kq * 2);
        *(uint2*)(smem + MHSH + off) = hi;
        *(uint2*)(smem + MHSL + off) = lo;
    }
    // b1: 512 floats = 256 float2 -> every thread loads one (R13 bug: tid<128)
    ((float2*)b1s)[tid] = ((const float2*)b1)[tid];
    if (tid < 32)  { ((float2*)b2s)[tid] = ((const float2*)b2)[tid]; }

    float outa[8][4];
#pragma unroll
    for (int j = 0; j < 8; j++)
#pragma unroll
        for (int q = 0; q < 4; q++) outa[j][q] = 0.f;

    for (int c = 0; c < 4; c++) {
        __syncthreads();   // previous chunk's readers done / hs+b1 visible (c==0)
        // ---- stage W1 chunk [128 x 128] ----
#pragma unroll
        for (int r = 0; r < 16; r++) {
            int idx = tid + 256 * r;
            int row = idx >> 5, kq = (idx & 31) * 4;
            float4 v = *(const float4*)&W1[(size_t)(c * 128 + row) * H_ + kq];
            uint2 hi, lo; split4(v, hi, lo);
            uint32_t off = (uint32_t)(row * LDW + kq * 2);
            *(uint2*)(smem + MW1H + off) = hi;
            *(uint2*)(smem + MW1L + off) = lo;
        }
        // ---- stage W2 chunk [64 x 128] ----
#pragma unroll
        for (int r = 0; r < 8; r++) {
            int idx = tid + 256 * r;
            int row = idx >> 5, kq = (idx & 31) * 4;
            float4 v = *(const float4*)&W2[(size_t)row * NH_ + c * 128 + kq];
            uint2 hi, lo; split4(v, hi, lo);
            uint32_t off = (uint32_t)(row * LDW + kq * 2);
            *(uint2*)(smem + MW2H + off) = hi;
            *(uint2*)(smem + MW2L + off) = lo;
        }
        __syncthreads();

        // ---- first gemm: hid[16 x 128] = hs_tile @ W1_c^T ----
        float hid[16][4];
#pragma unroll
        for (int j = 0; j < 16; j++)
#pragma unroll
            for (int q = 0; q < 4; q++) hid[j][q] = 0.f;

#pragma unroll
        for (int kt = 0; kt < 8; kt++) {
            uint32_t ahh[4], ahl[4];
            ldx4(ahh[0], ahh[1], ahh[2], ahh[3], sb + MHSH + a_off + kt * 32);
            ldx4(ahl[0], ahl[1], ahl[2], ahl[3], sb + MHSL + a_off + kt * 32);
#pragma unroll
            for (int nb = 0; nb < 8; nb++) {
                uint32_t wh[4], wl[4];
                ldx4(wh[0], wh[1], wh[2], wh[3],
                     sb + MW1H + b_off + (uint32_t)(nb * 16) * LDW + kt * 32);
                ldx4(wl[0], wl[1], wl[2], wl[3],
                     sb + MW1L + b_off + (uint32_t)(nb * 16) * LDW + kt * 32);
                mma16816(hid[2*nb],   ahh[0], ahh[1], ahh[2], ahh[3], wh[0], wh[1]);
                mma16816(hid[2*nb],   ahl[0], ahl[1], ahl[2], ahl[3], wh[0], wh[1]);
                mma16816(hid[2*nb],   ahh[0], ahh[1], ahh[2], ahh[3], wl[0], wl[1]);
                mma16816(hid[2*nb+1], ahh[0], ahh[1], ahh[2], ahh[3], wh[2], wh[3]);
                mma16816(hid[2*nb+1], ahl[0], ahl[1], ahl[2], ahl[3], wh[2], wh[3]);
                mma16816(hid[2*nb+1], ahh[0], ahh[1], ahh[2], ahh[3], wl[2], wl[3]);
            }
        }

        // ---- bias + relu ----
#pragma unroll
        for (int nf = 0; nf < 16; nf++) {
            int col = c * 128 + nf * 8 + (lane & 3) * 2;
            float bb0 = b1s[col], bb1 = b1s[col + 1];
            hid[nf][0] = fmaxf(hid[nf][0] + bb0, 0.f);
            hid[nf][1] = fmaxf(hid[nf][1] + bb1, 0.f);
            hid[nf][2] = fmaxf(hid[nf][2] + bb0, 0.f);
            hid[nf][3] = fmaxf(hid[nf][3] + bb1, 0.f);
        }

        // ---- second gemm: out += hid @ W2_c^T (C-frag -> A-frag) ----
#pragma unroll
        for (int t = 0; t < 8; t++) {
            float v0 = hid[2*t][0],   v1 = hid[2*t][1];
            float v2 = hid[2*t][2],   v3 = hid[2*t][3];
            float u0 = hid[2*t+1][0], u1 = hid[2*t+1][1];
            float u2 = hid[2*t+1][2], u3 = hid[2*t+1][3];
            float h0 = tobf(v0), h1 = tobf(v1), h2 = tobf(v2), h3 = tobf(v3);
            float g0 = tobf(u0), g1 = tobf(u1), g2 = tobf(u2), g3 = tobf(u3);
            uint32_t a0h = pkbf2(h0, h1), a1h = pkbf2(h2, h3);
            uint32_t a2h = pkbf2(g0, g1), a3h = pkbf2(g2, g3);
            uint32_t a0l = pkbf2(v0 - h0, v1 - h1), a1l = pkbf2(v2 - h2, v3 - h3);
            uint32_t a2l = pkbf2(u0 - g0, u1 - g1), a3l = pkbf2(u2 - g2, u3 - g3);
#pragma unroll
            for (int nb = 0; nb < 4; nb++) {
                uint32_t wh[4], wl[4];
                ldx4(wh[0], wh[1], wh[2], wh[3],
                     sb + MW2H + b_off + (uint32_t)(nb * 16) * LDW + t * 32);
                ldx4(wl[0], wl[1], wl[2], wl[3],
                     sb + MW2L + b_off + (uint32_t)(nb * 16) * LDW + t * 32);
                mma16816(outa[2*nb],   a0h, a1h, a2h, a3h, wh[0], wh[1]);
                mma16816(outa[2*nb],   a0l, a1l, a2l, a3l, wh[0], wh[1]);
                mma16816(outa[2*nb],   a0h, a1h, a2h, a3h, wl[0], wl[1]);
                mma16816(outa[2*nb+1], a0h, a1h, a2h, a3h, wh[2], wh[3]);
                mma16816(outa[2*nb+1], a0l, a1l, a2l, a3l, wh[2], wh[3]);
                mma16816(outa[2*nb+1], a0h, a1h, a2h, a3h, wl[2], wl[3]);
            }
        }
    }

    // ---- writeback out[16 x 64] + b2 ----
#pragma unroll
    for (int nf = 0; nf < 8; nf++) {
        int col = nf * 8 + (lane & 3) * 2;
        float bb0 = b2s[col], bb1 = b2s[col + 1];
        int row0 = m0 + w * 16 + (lane >> 2);
        float2 o0, o1;
        o0.x = outa[nf][0] + bb0; o0.y = outa[nf][1] + bb1;
        o1.x = outa[nf][2] + bb0; o1.y = outa[nf][3] + bb1;
        *(float2*)&out[(size_t)row0 * O_ + col] = o0;
        *(float2*)&out[(size_t)(row0 + 8) * O_ + col] = o1;
    }
}

// ---------------------------------------------------------------------------
// K2: LSTM scan (unchanged, proven). 128 CTAs, 256 threads, FFMA2.
// ---------------------------------------------------------------------------
__device__ __forceinline__ float sigf(float x) {
    return __fdividef(1.f, 1.f + __expf(-x));
}
__device__ __forceinline__ float tanhf_fast(float x) {
    return __fdividef(2.f, 1.f + __expf(-2.f * x)) - 1.f;
}

#define SC_KCSM 12
#define SC_KCRG (32 - SC_KCSM)
#define HS_PAD  (H_ + 4)
#define SCAN_SMEM ((SC_KCSM * G_ * 4 + 2 * HS_PAD + 2 * G_) * 4)

__global__ __launch_bounds__(256, 1) void k_scan2(float* __restrict__ hT_out,
                                                  float* __restrict__ cT_out)
{
    extern __shared__ float smf[];
    float4* W4s = (float4*)smf;
    float*  hsm = smf + SC_KCSM * G_ * 4;
    float*  gsm = hsm + 2 * HS_PAD;

    const int t  = threadIdx.x;
    const int g0 = t;
    const int g1 = t + 256;
    const int b0 = blockIdx.x * 2;

    for (int idx = t; idx < SC_KCSM * G_; idx += 256) W4s[idx] = g_wt4[idx];
    ulonglong2 wr0[SC_KCRG], wr1[SC_KCRG];
#pragma unroll
    for (int q = 0; q < SC_KCRG; q++) {
        wr0[q] = *(const ulonglong2*)&g_wt4[(SC_KCSM + q) * G_ + g0];
        wr1[q] = *(const ulonglong2*)&g_wt4[(SC_KCSM + q) * G_ + g1];
    }

    if (t < H_) { hsm[t] = 0.f; hsm[HS_PAD + t] = 0.f; }
    const int eb = t >> 7;
    const int ej = t & 127;
    float cst = 0.f;

    const float* xgp = g_xg + (size_t)b0 * G_;
    float x00 = xgp[g0],      x01 = xgp[G_ + g0];
    float x10 = xgp[g1],      x11 = xgp[G_ + g1];
    __syncthreads();

    for (int ts = 0; ts < T_; ts++) {
        int tn = (ts < T_ - 1) ? ts + 1 : ts;
        const float* xgn = g_xg + ((size_t)tn * B_ + b0) * G_;
        float n00 = xgn[g0], n01 = xgn[G_ + g0];
        float n10 = xgn[g1], n11 = xgn[G_ + g1];

        unsigned long long a00 = 0ull, a01 = 0ull, a10 = 0ull, a11 = 0ull;
#pragma unroll
        for (int kc = 0; kc < 32; kc++) {
            ulonglong2 w0 = (kc < SC_KCSM)
                ? *(const ulonglong2*)&W4s[kc * G_ + g0] : wr0[kc - SC_KCSM];
            ulonglong2 w1 = (kc < SC_KCSM)
                ? *(const ulonglong2*)&W4s[kc * G_ + g1] : wr1[kc - SC_KCSM];
            ulonglong2 h0 = *(const ulonglong2*)&hsm[kc * 4];
            ulonglong2 h1 = *(const ulonglong2*)&hsm[HS_PAD + kc * 4];
            fma2(a00, w0.x, h0.x); fma2(a00, w0.y, h0.y);
            fma2(a01, w0.x, h1.x); fma2(a01, w0.y, h1.y);
            fma2(a10, w1.x, h0.x); fma2(a10, w1.y, h0.y);
            fma2(a11, w1.x, h1.x); fma2(a11, w1.y, h1.y);
        }
        gsm[g0]       = hadd2(a00) + x00;
        gsm[G_ + g0]  = hadd2(a01) + x01;
        gsm[g1]       = hadd2(a10) + x10;
        gsm[G_ + g1]  = hadd2(a11) + x11;
        __syncthreads();

        {
            const float* gb = gsm + eb * G_;
            float ig = sigf(gb[ej]);
            float fg = sigf(gb[H_ + ej]);
            float gg = tanhf_fast(gb[2 * H_ + ej]);
            float og = sigf(gb[3 * H_ + ej]);
            cst = fmaf(fg, cst, ig * gg);
            float hv = og * tanhf_fast(cst);
            hsm[eb * HS_PAD + ej] = hv;
            g_hs[(size_t)(ts * B_ + b0 + eb) * H_ + ej] = hv;
        }
        __syncthreads();
        x00 = n00; x01 = n01; x10 = n10; x11 = n11;
    }

    hT_out[(b0 + eb) * H_ + ej] = hsm[eb * HS_PAD + ej];
    cT_out[(b0 + eb) * H_ + ej] = cst;
}

// ---------------------------------------------------------------------------
// Launcher
// ---------------------------------------------------------------------------
extern "C" void kernel_launch(void* const* d_in, const int* in_sizes, int n_in,
                              void* d_out, int out_size)
{
    const float* x    = (const float*)d_in[0];  // [T,B,I]
    const float* W_ih = (const float*)d_in[1];  // [512,64]
    const float* W_hh = (const float*)d_in[2];  // [512,128]
    const float* b_ih = (const float*)d_in[3];  // [512]
    const float* b_hh = (const float*)d_in[4];  // [512]
    const float* W1   = (const float*)d_in[5];  // [512,128]
    const float* b1   = (const float*)d_in[6];  // [512]
    const float* W2   = (const float*)d_in[7];  // [64,512]
    const float* b2   = (const float*)d_in[8];  // [64]

    float* out = (float*)d_out;                      // [T,B,64]
    float* hT  = out + (size_t)TB_ * O_;             // [1,256,128]
    float* cT  = hT + (size_t)B_ * H_;               // [1,256,128]

    float* xg; float* hs;
    cudaGetSymbolAddress((void**)&xg, g_xg);
    cudaGetSymbolAddress((void**)&hs, g_hs);

    static_assert(SCAN_SMEM <= 232448, "scan smem over limit");
    static_assert(MLP_SMEM <= 232448, "mlp smem over limit");
    cudaFuncSetAttribute(k_scan2, cudaFuncAttributeMaxDynamicSharedMemorySize,
                         SCAN_SMEM);
    cudaFuncSetAttribute(k_hgemm<false>,
                         cudaFuncAttributeMaxDynamicSharedMemorySize, HG_SMEM);
    cudaFuncSetAttribute(k_mlp,
                         cudaFuncAttributeMaxDynamicSharedMemorySize, MLP_SMEM);

    // K0: weight transpose for the scan
    k_twhh<<<(G_ * H_) / 256, 256>>>(W_hh);

    // K1: xg = x @ W_ih^T + (b_ih + b_hh)   [TB,512], K=64
    k_hgemm<false><<<dim3(TB_ / 128, G_ / 64), 256, HG_SMEM>>>(
        x, W_ih, b_ih, b_hh, xg, TB_, G_, I_);

    // K2: sequential LSTM scan -> g_hs, hT, cT
    k_scan2<<<B_ / 2, 256, SCAN_SMEM>>>(hT, cT);

    // K3+K4 fused: out = relu(hs@W1^T + b1)@W2^T + b2
    k_mlp<<<TB_ / 128, 256, MLP_SMEM>>>(hs, W1, b1, W2, b2, out);
}

// round 16
// speedup vs baseline: 1.0954x; 1.0954x over previous
#include <cuda_runtime.h>
#include <cuda_bf16.h>
#include <cstdint>
#include <cstddef>

// Problem constants
#define T_  2048
#define B_  256
#define I_  64
#define H_  128
#define G_  512          // 4*H gate rows
#define NH_ 512
#define O_  64
#define TB_ (T_ * B_)    // 524288

// ---------------------------------------------------------------------------
// f32x2 packed helpers (scan)
// ---------------------------------------------------------------------------
__device__ __forceinline__ void fma2(unsigned long long& d,
                                     unsigned long long a,
                                     unsigned long long b) {
    asm("fma.rn.f32x2 %0, %1, %2, %0;" : "+l"(d) : "l"(a), "l"(b));
}
__device__ __forceinline__ void unpack2(unsigned long long v, float& lo, float& hi) {
    asm("mov.b64 {%0, %1}, %2;" : "=f"(lo), "=f"(hi) : "l"(v));
}
__device__ __forceinline__ float hadd2(unsigned long long v) {
    float lo, hi; unpack2(v, lo, hi); return lo + hi;
}

__device__ __forceinline__ uint32_t smem_u32(const void* p) {
    uint32_t a;
    asm("{ .reg .u64 t; cvta.to.shared.u64 t, %1; cvt.u32.u64 %0, t; }"
        : "=r"(a) : "l"(p));
    return a;
}

// pack 2 floats -> bf16x2 (lo in low half)
__device__ __forceinline__ uint32_t pkbf2(float lo, float hi) {
    __nv_bfloat162 t = __floats2bfloat162_rn(lo, hi);
    return *(uint32_t*)&t;
}
__device__ __forceinline__ float tobf(float v) {
    return __bfloat162float(__float2bfloat16(v));
}

// split float4 into bf16 hi quad + bf16 lo (residual) quad
__device__ __forceinline__ void split4(float4 v, uint2& hi, uint2& lo) {
    float hx = tobf(v.x), hy = tobf(v.y), hz = tobf(v.z), hw = tobf(v.w);
    hi = make_uint2(pkbf2(hx, hy), pkbf2(hz, hw));
    lo = make_uint2(pkbf2(v.x - hx, v.y - hy), pkbf2(v.z - hz, v.w - hw));
}

// ldmatrix x4 (no trans)
__device__ __forceinline__ void ldx4(uint32_t& r0, uint32_t& r1,
                                     uint32_t& r2, uint32_t& r3, uint32_t addr) {
    asm volatile("ldmatrix.sync.aligned.m8n8.x4.shared.b16 {%0,%1,%2,%3}, [%4];"
        : "=r"(r0), "=r"(r1), "=r"(r2), "=r"(r3) : "r"(addr));
}

// bf16 mma m16n8k16, fp32 accumulate
__device__ __forceinline__ void mma16816(float* d,
                                         uint32_t a0, uint32_t a1,
                                         uint32_t a2, uint32_t a3,
                                         uint32_t b0, uint32_t b1) {
    asm volatile(
        "mma.sync.aligned.m16n8k16.row.col.f32.bf16.bf16.f32 "
        "{%0,%1,%2,%3}, {%4,%5,%6,%7}, {%8,%9}, {%0,%1,%2,%3};"
        : "+f"(d[0]), "+f"(d[1]), "+f"(d[2]), "+f"(d[3])
        : "r"(a0), "r"(a1), "r"(a2), "r"(a3), "r"(b0), "r"(b1));
}

// ---------------------------------------------------------------------------
// Scratch: __device__ globals (allocation-free rule).
// ---------------------------------------------------------------------------
__device__ float  g_xg[(size_t)TB_ * G_];   // gate preacts; reused as MLP hidden
__device__ float  g_hs[(size_t)TB_ * H_];   // all hidden states
__device__ float4 g_wt4[32 * G_];           // W_hh k-chunked

// ---------------------------------------------------------------------------
// K0: transpose W_hh [512,128] -> g_wt4
// ---------------------------------------------------------------------------
__global__ void k_twhh(const float* __restrict__ Whh) {
    int idx = blockIdx.x * 256 + threadIdx.x;
    int g = idx >> 7;
    int k = idx & 127;
    ((float*)g_wt4)[((k >> 2) * G_ + g) * 4 + (k & 3)] = Whh[idx];
}

// ---------------------------------------------------------------------------
// HMMA GEMM: C = A@W^T + bias (+bias2), opt relu. bf16 3-term split.
// CTA 128x64, BK=32, 8 warps (4m x 2n), double buffered.
// GRID IS N-MAJOR: n0 = blockIdx.x (fast), m0 = blockIdx.y (slow), so
// concurrent CTAs share m-blocks and A rows hit L2 instead of DRAM 8x.
// ---------------------------------------------------------------------------
#define LDB 80
#define ASZ (128 * LDB)
#define WSZ (64 * LDB)
#define BUF (2 * ASZ + 2 * WSZ)
#define HG_SMEM (2 * BUF)

template <bool RELU>
__global__ __launch_bounds__(256, 2) void k_hgemm(
    const float* __restrict__ A, const float* __restrict__ W,
    const float* __restrict__ bias, const float* __restrict__ bias2,
    float* __restrict__ C, int M, int N, int K)
{
    extern __shared__ char smem[];
    const uint32_t sb = smem_u32(smem);
    const uint32_t AHo = 0, ALo = ASZ, WHo = 2 * ASZ, WLo = 2 * ASZ + WSZ;

    const int tid  = threadIdx.x;
    const int wid  = tid >> 5;
    const int lane = tid & 31;
    const int wm   = wid & 3;
    const int wn   = wid >> 2;
    const int m0   = blockIdx.y * 128;      // n-major grid (L2 reuse of A)
    const int n0   = blockIdx.x * 64;

    const int am = tid >> 3;
    const int akq = (tid & 7) * 4;

    const uint32_t a_off = (uint32_t)((wm * 32 + (lane & 7) + ((lane >> 3) & 1) * 8) * LDB
                                      + (lane >> 4) * 16);
    const uint32_t b_off = (uint32_t)((wn * 32 + (lane & 7) + (lane >> 4) * 8) * LDB
                                      + ((lane >> 3) & 1) * 16);

    float acc[2][4][4];
#pragma unroll
    for (int i = 0; i < 2; i++)
#pragma unroll
        for (int j = 0; j < 4; j++)
#pragma unroll
            for (int q = 0; q < 4; q++) acc[i][j][q] = 0.f;

    float4 pa[4], pw[2];
#pragma unroll
    for (int r = 0; r < 4; r++)
        pa[r] = *(const float4*)&A[(size_t)(m0 + am + 32 * r) * K + akq];
#pragma unroll
    for (int r = 0; r < 2; r++) {
        int idx = tid + 256 * r;
        pw[r] = *(const float4*)&W[(size_t)(n0 + (idx >> 3)) * K + (idx & 7) * 4];
    }

    auto stage = [&](int buf, const float4* va, const float4* vw) {
        uint32_t bo = buf * BUF;
#pragma unroll
        for (int r = 0; r < 4; r++) {
            uint2 hi, lo;
            split4(va[r], hi, lo);
            uint32_t off = (uint32_t)((am + 32 * r) * LDB + akq * 2);
            *(uint2*)(smem + bo + AHo + off) = hi;
            *(uint2*)(smem + bo + ALo + off) = lo;
        }
#pragma unroll
        for (int r = 0; r < 2; r++) {
            int idx = tid + 256 * r;
            uint2 hi, lo;
            split4(vw[r], hi, lo);
            uint32_t off = (uint32_t)((idx >> 3) * LDB + (idx & 7) * 8);
            *(uint2*)(smem + bo + WHo + off) = hi;
            *(uint2*)(smem + bo + WLo + off) = lo;
        }
    };

    stage(0, pa, pw);
    __syncthreads();

    const int nt = K / 32;
    for (int t = 0; t < nt; t++) {
        const int cur = t & 1;
        const bool more = (t + 1 < nt);

        if (more) {
            const float* Ap = A + (t + 1) * 32;
            const float* Wp = W + (t + 1) * 32;
#pragma unroll
            for (int r = 0; r < 4; r++)
                pa[r] = *(const float4*)&Ap[(size_t)(m0 + am + 32 * r) * K + akq];
#pragma unroll
            for (int r = 0; r < 2; r++) {
                int idx = tid + 256 * r;
                pw[r] = *(const float4*)&Wp[(size_t)(n0 + (idx >> 3)) * K + (idx & 7) * 4];
            }
        }

        const uint32_t bufb = sb + cur * BUF;
#pragma unroll
        for (int s = 0; s < 2; s++) {
            const uint32_t ks = s * 32;
            uint32_t ah[2][4], al[2][4];
            ldx4(ah[0][0], ah[0][1], ah[0][2], ah[0][3], bufb + AHo + a_off + ks);
            ldx4(ah[1][0], ah[1][1], ah[1][2], ah[1][3], bufb + AHo + a_off + 16 * LDB + ks);
            ldx4(al[0][0], al[0][1], al[0][2], al[0][3], bufb + ALo + a_off + ks);
            ldx4(al[1][0], al[1][1], al[1][2], al[1][3], bufb + ALo + a_off + 16 * LDB + ks);
            uint32_t wh[2][4], wl[2][4];
            ldx4(wh[0][0], wh[0][1], wh[0][2], wh[0][3], bufb + WHo + b_off + ks);
            ldx4(wh[1][0], wh[1][1], wh[1][2], wh[1][3], bufb + WHo + b_off + 16 * LDB + ks);
            ldx4(wl[0][0], wl[0][1], wl[0][2], wl[0][3], bufb + WLo + b_off + ks);
            ldx4(wl[1][0], wl[1][1], wl[1][2], wl[1][3], bufb + WLo + b_off + 16 * LDB + ks);

#pragma unroll
            for (int mf = 0; mf < 2; mf++)
#pragma unroll
                for (int nf = 0; nf < 4; nf++) {
                    const int p = nf >> 1, q = (nf & 1) * 2;
                    mma16816(acc[mf][nf], ah[mf][0], ah[mf][1], ah[mf][2], ah[mf][3],
                             wh[p][q], wh[p][q + 1]);
                    mma16816(acc[mf][nf], al[mf][0], al[mf][1], al[mf][2], al[mf][3],
                             wh[p][q], wh[p][q + 1]);
                    mma16816(acc[mf][nf], ah[mf][0], ah[mf][1], ah[mf][2], ah[mf][3],
                             wl[p][q], wl[p][q + 1]);
                }
        }

        if (more) {
            stage(cur ^ 1, pa, pw);
            __syncthreads();
        }
    }

#pragma unroll
    for (int mf = 0; mf < 2; mf++) {
#pragma unroll
        for (int nf = 0; nf < 4; nf++) {
            int col = n0 + wn * 32 + nf * 8 + (lane & 3) * 2;
            float b0v = bias[col], b1v = bias[col + 1];
            if (bias2) { b0v += bias2[col]; b1v += bias2[col + 1]; }
            int row0 = m0 + wm * 32 + mf * 16 + (lane >> 2);
            float2 o0, o1;
            o0.x = acc[mf][nf][0] + b0v; o0.y = acc[mf][nf][1] + b1v;
            o1.x = acc[mf][nf][2] + b0v; o1.y = acc[mf][nf][3] + b1v;
            if (RELU) {
                o0.x = fmaxf(o0.x, 0.f); o0.y = fmaxf(o0.y, 0.f);
                o1.x = fmaxf(o1.x, 0.f); o1.y = fmaxf(o1.y, 0.f);
            }
            *(float2*)&C[(size_t)row0 * N + col] = o0;
            *(float2*)&C[(size_t)(row0 + 8) * N + col] = o1;
        }
    }
}

// ---------------------------------------------------------------------------
// K2: LSTM scan. 128 CTAs (2 batch rows), 256 threads (2 gate rows each),
// k-packed FFMA2. 22/32 weight chunks in registers, 10 in smem
// (crossbar wf/step 1280 -> 1152; FFMA2 RF-bank rt=3 floor ~1536).
// ---------------------------------------------------------------------------
__device__ __forceinline__ float sigf(float x) {
    return __fdividef(1.f, 1.f + __expf(-x));
}
__device__ __forceinline__ float tanhf_fast(float x) {
    return __fdividef(2.f, 1.f + __expf(-2.f * x)) - 1.f;
}

#define SC_KCSM 10
#define SC_KCRG (32 - SC_KCSM)
#define HS_PAD  (H_ + 4)
#define SCAN_SMEM ((SC_KCSM * G_ * 4 + 2 * HS_PAD + 2 * G_) * 4)

__global__ __launch_bounds__(256, 1) void k_scan2(float* __restrict__ hT_out,
                                                  float* __restrict__ cT_out)
{
    extern __shared__ float smf[];
    float4* W4s = (float4*)smf;
    float*  hsm = smf + SC_KCSM * G_ * 4;
    float*  gsm = hsm + 2 * HS_PAD;

    const int t  = threadIdx.x;
    const int g0 = t;
    const int g1 = t + 256;
    const int b0 = blockIdx.x * 2;

    for (int idx = t; idx < SC_KCSM * G_; idx += 256) W4s[idx] = g_wt4[idx];
    ulonglong2 wr0[SC_KCRG], wr1[SC_KCRG];
#pragma unroll
    for (int q = 0; q < SC_KCRG; q++) {
        wr0[q] = *(const ulonglong2*)&g_wt4[(SC_KCSM + q) * G_ + g0];
        wr1[q] = *(const ulonglong2*)&g_wt4[(SC_KCSM + q) * G_ + g1];
    }

    if (t < H_) { hsm[t] = 0.f; hsm[HS_PAD + t] = 0.f; }
    const int eb = t >> 7;
    const int ej = t & 127;
    float cst = 0.f;

    const float* xgp = g_xg + (size_t)b0 * G_;
    float x00 = xgp[g0],      x01 = xgp[G_ + g0];
    float x10 = xgp[g1],      x11 = xgp[G_ + g1];
    __syncthreads();

    for (int ts = 0; ts < T_; ts++) {
        int tn = (ts < T_ - 1) ? ts + 1 : ts;
        const float* xgn = g_xg + ((size_t)tn * B_ + b0) * G_;
        float n00 = xgn[g0], n01 = xgn[G_ + g0];
        float n10 = xgn[g1], n11 = xgn[G_ + g1];

        unsigned long long a00 = 0ull, a01 = 0ull, a10 = 0ull, a11 = 0ull;
#pragma unroll
        for (int kc = 0; kc < 32; kc++) {
            ulonglong2 w0 = (kc < SC_KCSM)
                ? *(const ulonglong2*)&W4s[kc * G_ + g0] : wr0[kc - SC_KCSM];
            ulonglong2 w1 = (kc < SC_KCSM)
                ? *(const ulonglong2*)&W4s[kc * G_ + g1] : wr1[kc - SC_KCSM];
            ulonglong2 h0 = *(const ulonglong2*)&hsm[kc * 4];
            ulonglong2 h1 = *(const ulonglong2*)&hsm[HS_PAD + kc * 4];
            fma2(a00, w0.x, h0.x); fma2(a00, w0.y, h0.y);
            fma2(a01, w0.x, h1.x); fma2(a01, w0.y, h1.y);
            fma2(a10, w1.x, h0.x); fma2(a10, w1.y, h0.y);
            fma2(a11, w1.x, h1.x); fma2(a11, w1.y, h1.y);
        }
        gsm[g0]       = hadd2(a00) + x00;
        gsm[G_ + g0]  = hadd2(a01) + x01;
        gsm[g1]       = hadd2(a10) + x10;
        gsm[G_ + g1]  = hadd2(a11) + x11;
        __syncthreads();

        {
            const float* gb = gsm + eb * G_;
            float ig = sigf(gb[ej]);
            float fg = sigf(gb[H_ + ej]);
            float gg = tanhf_fast(gb[2 * H_ + ej]);
            float og = sigf(gb[3 * H_ + ej]);
            cst = fmaf(fg, cst, ig * gg);
            float hv = og * tanhf_fast(cst);
            hsm[eb * HS_PAD + ej] = hv;
            g_hs[(size_t)(ts * B_ + b0 + eb) * H_ + ej] = hv;
        }
        __syncthreads();
        x00 = n00; x01 = n01; x10 = n10; x11 = n11;
    }

    hT_out[(b0 + eb) * H_ + ej] = hsm[eb * HS_PAD + ej];
    cT_out[(b0 + eb) * H_ + ej] = cst;
}

// ---------------------------------------------------------------------------
// Launcher
// ---------------------------------------------------------------------------
extern "C" void kernel_launch(void* const* d_in, const int* in_sizes, int n_in,
                              void* d_out, int out_size)
{
    const float* x    = (const float*)d_in[0];  // [T,B,I]
    const float* W_ih = (const float*)d_in[1];  // [512,64]
    const float* W_hh = (const float*)d_in[2];  // [512,128]
    const float* b_ih = (const float*)d_in[3];  // [512]
    const float* b_hh = (const float*)d_in[4];  // [512]
    const float* W1   = (const float*)d_in[5];  // [512,128]
    const float* b1   = (const float*)d_in[6];  // [512]
    const float* W2   = (const float*)d_in[7];  // [64,512]
    const float* b2   = (const float*)d_in[8];  // [64]

    float* out = (float*)d_out;                      // [T,B,64]
    float* hT  = out + (size_t)TB_ * O_;             // [1,256,128]
    float* cT  = hT + (size_t)B_ * H_;               // [1,256,128]

    float* xg; float* hs;
    cudaGetSymbolAddress((void**)&xg, g_xg);
    cudaGetSymbolAddress((void**)&hs, g_hs);

    static_assert(SCAN_SMEM <= 232448, "scan smem over limit");
    cudaFuncSetAttribute(k_scan2, cudaFuncAttributeMaxDynamicSharedMemorySize,
                         SCAN_SMEM);
    cudaFuncSetAttribute(k_hgemm<false>,
                         cudaFuncAttributeMaxDynamicSharedMemorySize, HG_SMEM);
    cudaFuncSetAttribute(k_hgemm<true>,
                         cudaFuncAttributeMaxDynamicSharedMemorySize, HG_SMEM);

    // K0: weight transpose for the scan
    k_twhh<<<(G_ * H_) / 256, 256>>>(W_hh);

    // K1: xg = x @ W_ih^T + (b_ih + b_hh)   [TB,512], K=64  (n-major grid)
    k_hgemm<false><<<dim3(G_ / 64, TB_ / 128), 256, HG_SMEM>>>(
        x, W_ih, b_ih, b_hh, xg, TB_, G_, I_);

    // K2: sequential LSTM scan -> g_hs, hT, cT
    k_scan2<<<B_ / 2, 256, SCAN_SMEM>>>(hT, cT);

    // K3: hidden = relu(hs @ W1^T + b1)   [TB,512], K=128  (n-major grid)
    k_hgemm<true><<<dim3(NH_ / 64, TB_ / 128), 256, HG_SMEM>>>(
        hs, W1, b1, nullptr, xg, TB_, NH_, H_);

    // K4: out = hidden @ W2^T + b2   [TB,64], K=512
    k_hgemm<false><<<dim3(O_ / 64, TB_ / 128), 256, HG_SMEM>>>(
        xg, W2, b2, nullptr, out, TB_, O_, NH_);
}

// round 17
// speedup vs baseline: 1.4064x; 1.2839x over previous
#include <cuda_runtime.h>
#include <cuda_bf16.h>
#include <cstdint>
#include <cstddef>

// Problem constants
#define T_  2048
#define B_  256
#define I_  64
#define H_  128
#define G_  512          // 4*H gate rows
#define NH_ 512
#define O_  64
#define TB_ (T_ * B_)    // 524288

// ---------------------------------------------------------------------------
// f32x2 packed helpers (scan)
// ---------------------------------------------------------------------------
__device__ __forceinline__ void fma2(unsigned long long& d,
                                     unsigned long long a,
                                     unsigned long long b) {
    asm("fma.rn.f32x2 %0, %1, %2, %0;" : "+l"(d) : "l"(a), "l"(b));
}
__device__ __forceinline__ void unpack2(unsigned long long v, float& lo, float& hi) {
    asm("mov.b64 {%0, %1}, %2;" : "=f"(lo), "=f"(hi) : "l"(v));
}
__device__ __forceinline__ float hadd2(unsigned long long v) {
    float lo, hi; unpack2(v, lo, hi); return lo + hi;
}

__device__ __forceinline__ uint32_t smem_u32(const void* p) {
    uint32_t a;
    asm("{ .reg .u64 t; cvta.to.shared.u64 t, %1; cvt.u32.u64 %0, t; }"
        : "=r"(a) : "l"(p));
    return a;
}

// pack 2 floats -> bf16x2 (lo in low half)
__device__ __forceinline__ uint32_t pkbf2(float lo, float hi) {
    __nv_bfloat162 t = __floats2bfloat162_rn(lo, hi);
    return *(uint32_t*)&t;
}
__device__ __forceinline__ float tobf(float v) {
    return __bfloat162float(__float2bfloat16(v));
}

// split float4 into bf16 hi quad + bf16 lo (residual) quad
__device__ __forceinline__ void split4(float4 v, uint2& hi, uint2& lo) {
    float hx = tobf(v.x), hy = tobf(v.y), hz = tobf(v.z), hw = tobf(v.w);
    hi = make_uint2(pkbf2(hx, hy), pkbf2(hz, hw));
    lo = make_uint2(pkbf2(v.x - hx, v.y - hy), pkbf2(v.z - hz, v.w - hw));
}

// ldmatrix x4 (no trans)
__device__ __forceinline__ void ldx4(uint32_t& r0, uint32_t& r1,
                                     uint32_t& r2, uint32_t& r3, uint32_t addr) {
    asm volatile("ldmatrix.sync.aligned.m8n8.x4.shared.b16 {%0,%1,%2,%3}, [%4];"
        : "=r"(r0), "=r"(r1), "=r"(r2), "=r"(r3) : "r"(addr));
}

// bf16 mma m16n8k16, fp32 accumulate
__device__ __forceinline__ void mma16816(float* d,
                                         uint32_t a0, uint32_t a1,
                                         uint32_t a2, uint32_t a3,
                                         uint32_t b0, uint32_t b1) {
    asm volatile(
        "mma.sync.aligned.m16n8k16.row.col.f32.bf16.bf16.f32 "
        "{%0,%1,%2,%3}, {%4,%5,%6,%7}, {%8,%9}, {%0,%1,%2,%3};"
        : "+f"(d[0]), "+f"(d[1]), "+f"(d[2]), "+f"(d[3])
        : "r"(a0), "r"(a1), "r"(a2), "r"(a3), "r"(b0), "r"(b1));
}

// ---------------------------------------------------------------------------
// Scratch: __device__ globals (allocation-free rule).
// ---------------------------------------------------------------------------
__device__ float  g_xg[(size_t)TB_ * G_];   // gate preacts; reused as MLP hidden
__device__ float  g_hs[(size_t)TB_ * H_];   // all hidden states
__device__ float4 g_wt4[32 * G_];           // W_hh k-chunked

// ---------------------------------------------------------------------------
// K0: transpose W_hh [512,128] -> g_wt4
// ---------------------------------------------------------------------------
__global__ void k_twhh(const float* __restrict__ Whh) {
    int idx = blockIdx.x * 256 + threadIdx.x;
    int g = idx >> 7;
    int k = idx & 127;
    ((float*)g_wt4)[((k >> 2) * G_ + g) * 4 + (k & 3)] = Whh[idx];
}

// ---------------------------------------------------------------------------
// HMMA GEMM: C = A@W^T + bias (+bias2), opt relu. bf16 3-term split.
// CTA 128x64, BK=32, 8 warps (4m x 2n), double buffered.
// GRID IS N-MAJOR: n0 = blockIdx.x (fast), m0 = blockIdx.y (slow), so
// concurrent CTAs share m-blocks and A rows hit L2 instead of DRAM 8x.
// ---------------------------------------------------------------------------
#define LDB 80
#define ASZ (128 * LDB)
#define WSZ (64 * LDB)
#define BUF (2 * ASZ + 2 * WSZ)
#define HG_SMEM (2 * BUF)

template <bool RELU>
__global__ __launch_bounds__(256, 2) void k_hgemm(
    const float* __restrict__ A, const float* __restrict__ W,
    const float* __restrict__ bias, const float* __restrict__ bias2,
    float* __restrict__ C, int M, int N, int K)
{
    extern __shared__ char smem[];
    const uint32_t sb = smem_u32(smem);
    const uint32_t AHo = 0, ALo = ASZ, WHo = 2 * ASZ, WLo = 2 * ASZ + WSZ;

    const int tid  = threadIdx.x;
    const int wid  = tid >> 5;
    const int lane = tid & 31;
    const int wm   = wid & 3;
    const int wn   = wid >> 2;
    const int m0   = blockIdx.y * 128;      // n-major grid (L2 reuse of A)
    const int n0   = blockIdx.x * 64;

    const int am = tid >> 3;
    const int akq = (tid & 7) * 4;

    const uint32_t a_off = (uint32_t)((wm * 32 + (lane & 7) + ((lane >> 3) & 1) * 8) * LDB
                                      + (lane >> 4) * 16);
    const uint32_t b_off = (uint32_t)((wn * 32 + (lane & 7) + (lane >> 4) * 8) * LDB
                                      + ((lane >> 3) & 1) * 16);

    float acc[2][4][4];
#pragma unroll
    for (int i = 0; i < 2; i++)
#pragma unroll
        for (int j = 0; j < 4; j++)
#pragma unroll
            for (int q = 0; q < 4; q++) acc[i][j][q] = 0.f;

    float4 pa[4], pw[2];
#pragma unroll
    for (int r = 0; r < 4; r++)
        pa[r] = *(const float4*)&A[(size_t)(m0 + am + 32 * r) * K + akq];
#pragma unroll
    for (int r = 0; r < 2; r++) {
        int idx = tid + 256 * r;
        pw[r] = *(const float4*)&W[(size_t)(n0 + (idx >> 3)) * K + (idx & 7) * 4];
    }

    auto stage = [&](int buf, const float4* va, const float4* vw) {
        uint32_t bo = buf * BUF;
#pragma unroll
        for (int r = 0; r < 4; r++) {
            uint2 hi, lo;
            split4(va[r], hi, lo);
            uint32_t off = (uint32_t)((am + 32 * r) * LDB + akq * 2);
            *(uint2*)(smem + bo + AHo + off) = hi;
            *(uint2*)(smem + bo + ALo + off) = lo;
        }
#pragma unroll
        for (int r = 0; r < 2; r++) {
            int idx = tid + 256 * r;
            uint2 hi, lo;
            split4(vw[r], hi, lo);
            uint32_t off = (uint32_t)((idx >> 3) * LDB + (idx & 7) * 8);
            *(uint2*)(smem + bo + WHo + off) = hi;
            *(uint2*)(smem + bo + WLo + off) = lo;
        }
    };

    stage(0, pa, pw);
    __syncthreads();

    const int nt = K / 32;
    for (int t = 0; t < nt; t++) {
        const int cur = t & 1;
        const bool more = (t + 1 < nt);

        if (more) {
            const float* Ap = A + (t + 1) * 32;
            const float* Wp = W + (t + 1) * 32;
#pragma unroll
            for (int r = 0; r < 4; r++)
                pa[r] = *(const float4*)&Ap[(size_t)(m0 + am + 32 * r) * K + akq];
#pragma unroll
            for (int r = 0; r < 2; r++) {
                int idx = tid + 256 * r;
                pw[r] = *(const float4*)&Wp[(size_t)(n0 + (idx >> 3)) * K + (idx & 7) * 4];
            }
        }

        const uint32_t bufb = sb + cur * BUF;
#pragma unroll
        for (int s = 0; s < 2; s++) {
            const uint32_t ks = s * 32;
            uint32_t ah[2][4], al[2][4];
            ldx4(ah[0][0], ah[0][1], ah[0][2], ah[0][3], bufb + AHo + a_off + ks);
            ldx4(ah[1][0], ah[1][1], ah[1][2], ah[1][3], bufb + AHo + a_off + 16 * LDB + ks);
            ldx4(al[0][0], al[0][1], al[0][2], al[0][3], bufb + ALo + a_off + ks);
            ldx4(al[1][0], al[1][1], al[1][2], al[1][3], bufb + ALo + a_off + 16 * LDB + ks);
            uint32_t wh[2][4], wl[2][4];
            ldx4(wh[0][0], wh[0][1], wh[0][2], wh[0][3], bufb + WHo + b_off + ks);
            ldx4(wh[1][0], wh[1][1], wh[1][2], wh[1][3], bufb + WHo + b_off + 16 * LDB + ks);
            ldx4(wl[0][0], wl[0][1], wl[0][2], wl[0][3], bufb + WLo + b_off + ks);
            ldx4(wl[1][0], wl[1][1], wl[1][2], wl[1][3], bufb + WLo + b_off + 16 * LDB + ks);

#pragma unroll
            for (int mf = 0; mf < 2; mf++)
#pragma unroll
                for (int nf = 0; nf < 4; nf++) {
                    const int p = nf >> 1, q = (nf & 1) * 2;
                    mma16816(acc[mf][nf], ah[mf][0], ah[mf][1], ah[mf][2], ah[mf][3],
                             wh[p][q], wh[p][q + 1]);
                    mma16816(acc[mf][nf], al[mf][0], al[mf][1], al[mf][2], al[mf][3],
                             wh[p][q], wh[p][q + 1]);
                    mma16816(acc[mf][nf], ah[mf][0], ah[mf][1], ah[mf][2], ah[mf][3],
                             wl[p][q], wl[p][q + 1]);
                }
        }

        if (more) {
            stage(cur ^ 1, pa, pw);
            __syncthreads();
        }
    }

#pragma unroll
    for (int mf = 0; mf < 2; mf++) {
#pragma unroll
        for (int nf = 0; nf < 4; nf++) {
            int col = n0 + wn * 32 + nf * 8 + (lane & 3) * 2;
            float b0v = bias[col], b1v = bias[col + 1];
            if (bias2) { b0v += bias2[col]; b1v += bias2[col + 1]; }
            int row0 = m0 + wm * 32 + mf * 16 + (lane >> 2);
            float2 o0, o1;
            o0.x = acc[mf][nf][0] + b0v; o0.y = acc[mf][nf][1] + b1v;
            o1.x = acc[mf][nf][2] + b0v; o1.y = acc[mf][nf][3] + b1v;
            if (RELU) {
                o0.x = fmaxf(o0.x, 0.f); o0.y = fmaxf(o0.y, 0.f);
                o1.x = fmaxf(o1.x, 0.f); o1.y = fmaxf(o1.y, 0.f);
            }
            *(float2*)&C[(size_t)row0 * N + col] = o0;
            *(float2*)&C[(size_t)(row0 + 8) * N + col] = o1;
        }
    }
}

// ---------------------------------------------------------------------------
// K2: LSTM scan. 128 CTAs (2 batch rows), 256 threads (2 gate rows each),
// k-packed FFMA2. SC_KCSM=12 (PROVEN R12 config; 10 spilled registers).
// ---------------------------------------------------------------------------
__device__ __forceinline__ float sigf(float x) {
    return __fdividef(1.f, 1.f + __expf(-x));
}
__device__ __forceinline__ float tanhf_fast(float x) {
    return __fdividef(2.f, 1.f + __expf(-2.f * x)) - 1.f;
}

#define SC_KCSM 12
#define SC_KCRG (32 - SC_KCSM)
#define HS_PAD  (H_ + 4)
#define SCAN_SMEM ((SC_KCSM * G_ * 4 + 2 * HS_PAD + 2 * G_) * 4)

__global__ __launch_bounds__(256, 1) void k_scan2(float* __restrict__ hT_out,
                                                  float* __restrict__ cT_out)
{
    extern __shared__ float smf[];
    float4* W4s = (float4*)smf;
    float*  hsm = smf + SC_KCSM * G_ * 4;
    float*  gsm = hsm + 2 * HS_PAD;

    const int t  = threadIdx.x;
    const int g0 = t;
    const int g1 = t + 256;
    const int b0 = blockIdx.x * 2;

    for (int idx = t; idx < SC_KCSM * G_; idx += 256) W4s[idx] = g_wt4[idx];
    ulonglong2 wr0[SC_KCRG], wr1[SC_KCRG];
#pragma unroll
    for (int q = 0; q < SC_KCRG; q++) {
        wr0[q] = *(const ulonglong2*)&g_wt4[(SC_KCSM + q) * G_ + g0];
        wr1[q] = *(const ulonglong2*)&g_wt4[(SC_KCSM + q) * G_ + g1];
    }

    if (t < H_) { hsm[t] = 0.f; hsm[HS_PAD + t] = 0.f; }
    const int eb = t >> 7;
    const int ej = t & 127;
    float cst = 0.f;

    const float* xgp = g_xg + (size_t)b0 * G_;
    float x00 = xgp[g0],      x01 = xgp[G_ + g0];
    float x10 = xgp[g1],      x11 = xgp[G_ + g1];
    __syncthreads();

    for (int ts = 0; ts < T_; ts++) {
        int tn = (ts < T_ - 1) ? ts + 1 : ts;
        const float* xgn = g_xg + ((size_t)tn * B_ + b0) * G_;
        float n00 = xgn[g0], n01 = xgn[G_ + g0];
        float n10 = xgn[g1], n11 = xgn[G_ + g1];

        unsigned long long a00 = 0ull, a01 = 0ull, a10 = 0ull, a11 = 0ull;
#pragma unroll
        for (int kc = 0; kc < 32; kc++) {
            ulonglong2 w0 = (kc < SC_KCSM)
                ? *(const ulonglong2*)&W4s[kc * G_ + g0] : wr0[kc - SC_KCSM];
            ulonglong2 w1 = (kc < SC_KCSM)
                ? *(const ulonglong2*)&W4s[kc * G_ + g1] : wr1[kc - SC_KCSM];
            ulonglong2 h0 = *(const ulonglong2*)&hsm[kc * 4];
            ulonglong2 h1 = *(const ulonglong2*)&hsm[HS_PAD + kc * 4];
            fma2(a00, w0.x, h0.x); fma2(a00, w0.y, h0.y);
            fma2(a01, w0.x, h1.x); fma2(a01, w0.y, h1.y);
            fma2(a10, w1.x, h0.x); fma2(a10, w1.y, h0.y);
            fma2(a11, w1.x, h1.x); fma2(a11, w1.y, h1.y);
        }
        gsm[g0]       = hadd2(a00) + x00;
        gsm[G_ + g0]  = hadd2(a01) + x01;
        gsm[g1]       = hadd2(a10) + x10;
        gsm[G_ + g1]  = hadd2(a11) + x11;
        __syncthreads();

        {
            const float* gb = gsm + eb * G_;
            float ig = sigf(gb[ej]);
            float fg = sigf(gb[H_ + ej]);
            float gg = tanhf_fast(gb[2 * H_ + ej]);
            float og = sigf(gb[3 * H_ + ej]);
            cst = fmaf(fg, cst, ig * gg);
            float hv = og * tanhf_fast(cst);
            hsm[eb * HS_PAD + ej] = hv;
            g_hs[(size_t)(ts * B_ + b0 + eb) * H_ + ej] = hv;
        }
        __syncthreads();
        x00 = n00; x01 = n01; x10 = n10; x11 = n11;
    }

    hT_out[(b0 + eb) * H_ + ej] = hsm[eb * HS_PAD + ej];
    cT_out[(b0 + eb) * H_ + ej] = cst;
}

// ---------------------------------------------------------------------------
// Launcher
// ---------------------------------------------------------------------------
extern "C" void kernel_launch(void* const* d_in, const int* in_sizes, int n_in,
                              void* d_out, int out_size)
{
    const float* x    = (const float*)d_in[0];  // [T,B,I]
    const float* W_ih = (const float*)d_in[1];  // [512,64]
    const float* W_hh = (const float*)d_in[2];  // [512,128]
    const float* b_ih = (const float*)d_in[3];  // [512]
    const float* b_hh = (const float*)d_in[4];  // [512]
    const float* W1   = (const float*)d_in[5];  // [512,128]
    const float* b1   = (const float*)d_in[6];  // [512]
    const float* W2   = (const float*)d_in[7];  // [64,512]
    const float* b2   = (const float*)d_in[8];  // [64]

    float* out = (float*)d_out;                      // [T,B,64]
    float* hT  = out + (size_t)TB_ * O_;             // [1,256,128]
    float* cT  = hT + (size_t)B_ * H_;               // [1,256,128]

    float* xg; float* hs;
    cudaGetSymbolAddress((void**)&xg, g_xg);
    cudaGetSymbolAddress((void**)&hs, g_hs);

    static_assert(SCAN_SMEM <= 232448, "scan smem over limit");
    cudaFuncSetAttribute(k_scan2, cudaFuncAttributeMaxDynamicSharedMemorySize,
                         SCAN_SMEM);
    cudaFuncSetAttribute(k_hgemm<false>,
                         cudaFuncAttributeMaxDynamicSharedMemorySize, HG_SMEM);
    cudaFuncSetAttribute(k_hgemm<true>,
                         cudaFuncAttributeMaxDynamicSharedMemorySize, HG_SMEM);

    // K0: weight transpose for the scan
    k_twhh<<<(G_ * H_) / 256, 256>>>(W_hh);

    // K1: xg = x @ W_ih^T + (b_ih + b_hh)   [TB,512], K=64  (n-major grid)
    k_hgemm<false><<<dim3(G_ / 64, TB_ / 128), 256, HG_SMEM>>>(
        x, W_ih, b_ih, b_hh, xg, TB_, G_, I_);

    // K2: sequential LSTM scan -> g_hs, hT, cT
    k_scan2<<<B_ / 2, 256, SCAN_SMEM>>>(hT, cT);

    // K3: hidden = relu(hs @ W1^T + b1)   [TB,512], K=128  (n-major grid)
    k_hgemm<true><<<dim3(NH_ / 64, TB_ / 128), 256, HG_SMEM>>>(
        hs, W1, b1, nullptr, xg, TB_, NH_, H_);

    // K4: out = hidden @ W2^T + b2   [TB,64], K=512
    k_hgemm<false><<<dim3(O_ / 64, TB_ / 128), 256, HG_SMEM>>>(
        xg, W2, b2, nullptr, out, TB_, O_, NH_);
}